// round 7
// baseline (speedup 1.0000x reference)
#include <cuda_runtime.h>

// Problem constants (fixed by the dataset)
#define HH   1024
#define WW   2048
#define GWC  2052            // padded row stride in CELLS (even -> float4-aligned pairs)
#define GH   (HH + 2)        // padded grid height = 1026
#define NCELL (GH * GWC)     // 2,105,352 cells (float2 each, ~16.8 MB)
#define NPIX (HH * WW)       // 2,097,152
#define COUT 64
#define BN_EPS 1e-5f
#define STATS_BLOCKS 592
#define TILE 256

// Packed f32x2 FMA (Blackwell FFMA2 — PTX-only)
#define FMA2(d, a, b, c) \
    asm("fma.rn.f32x2 %0, %1, %2, %3;" : "=l"(d) : "l"(a), "l"(b), "l"(c))

// Scratch (static __device__ arrays — no allocation)
// Each cell: .x = feature value (0 if empty), .y = output row index bits (-1 if empty)
__device__ float2 g_cell[NCELL];             // 16.8 MB interleaved grid (L2-resident)
__device__ float  g_part[STATS_BLOCKS * 54]; // per-block stat partials
__device__ float  g_wf[9 * COUT];            // BN-folded weights
__device__ float  g_bf[COUT];                // BN-folded bias
__device__ int    g_ctr;                     // last-block-done counter

// ---------------------------------------------------------------------------
// K0: fill the cell grid with (0.0f, -1) + reset the stats counter
// ---------------------------------------------------------------------------
__global__ void k_zero() {
    if (blockIdx.x == 0 && threadIdx.x == 0) g_ctr = 0;
    const int n4 = NCELL / 2;          // float4 = 2 cells
    const float neg1 = __int_as_float(-1);
    float4 z = make_float4(0.f, neg1, 0.f, neg1);
    const int tid = blockIdx.x * blockDim.x + threadIdx.x;
    const int str = gridDim.x * blockDim.x;
    for (int j = tid; j < n4; j += str)
        reinterpret_cast<float4*>(g_cell)[j] = z;
}

// ---------------------------------------------------------------------------
// K1: scatter (feature, row-index) into the cell grid — ONE 8 B store/point
// ---------------------------------------------------------------------------
__global__ void k_scatter(const int2* __restrict__ coords,
                          const float* __restrict__ feats, int n) {
    int i = blockIdx.x * blockDim.x + threadIdx.x;
    if (i < n) {
        int2 c = coords[i];                        // c.x = y, c.y = x
        g_cell[(c.x + 1) * GWC + (c.y + 1)] = make_float2(feats[i], __int_as_float(i));
    }
}

// ---------------------------------------------------------------------------
// K2: DENSE vectorized stats scan — each thread handles 2 consecutive pixels
//     (x even) with 6 aligned LDG.128 (3 rows x 2 float4 = 4 cells). Mask
//     comes from the center-row cells' .y. Accumulates sum9[9] + upper-tri
//     second moment M[45] in fixed order (deterministic). LAST block reduces
//     partials + folds BN into the conv weights.
// ---------------------------------------------------------------------------
__global__ __launch_bounds__(256) void k_stats(
        const float* __restrict__ weight,   // [9,1,64]
        const float* __restrict__ gamma,
        const float* __restrict__ beta, int n) {
    float acc[54];
#pragma unroll
    for (int i = 0; i < 54; i++) acc[i] = 0.f;

    const int tid    = blockIdx.x * blockDim.x + threadIdx.x;
    const int stride = gridDim.x * blockDim.x;
    const int npair  = NPIX / 2;

    for (int P = tid; P < npair; P += stride) {
        const int q = P * 2;
        const int y = q >> 11;           // WW = 2048
        const int x = q & (WW - 1);      // even
        const float2* base = g_cell + y * GWC + x;   // tap rows y..y+2, cells x..x+3

        float v[3][4];                   // tap values per row
        float mb[2];                     // center-row idx bits for the 2 pixels
#pragma unroll
        for (int r = 0; r < 3; r++) {
            float4 u = *reinterpret_cast<const float4*>(base + r * GWC);      // cells x, x+1
            float4 w = *reinterpret_cast<const float4*>(base + r * GWC + 2);  // cells x+2, x+3
            v[r][0] = u.x; v[r][1] = u.z; v[r][2] = w.x; v[r][3] = w.z;
            if (r == 1) { mb[0] = u.w; mb[1] = w.y; }   // centers: cells x+1, x+2
        }

#pragma unroll
        for (int i = 0; i < 2; i++) {
            const float m = (__float_as_int(mb[i]) >= 0) ? 1.f : 0.f;
            float s[9];
#pragma unroll
            for (int r = 0; r < 3; r++)
#pragma unroll
                for (int c = 0; c < 3; c++)
                    s[r * 3 + c] = v[r][i + c] * m;
#pragma unroll
            for (int k = 0; k < 9; k++) acc[k] += s[k];
            int idx = 9;
#pragma unroll
            for (int j = 0; j < 9; j++)
#pragma unroll
                for (int k = j; k < 9; k++) acc[idx++] += s[j] * s[k];
        }
    }

    // block reduction: warp shfl -> shared -> per-block partial
    __shared__ float red[54 * 8];
    const int w = threadIdx.x >> 5, lane = threadIdx.x & 31;
#pragma unroll
    for (int i = 0; i < 54; i++) {
        float vv = acc[i];
#pragma unroll
        for (int o = 16; o; o >>= 1) vv += __shfl_xor_sync(0xffffffffu, vv, o);
        if (lane == 0) red[i * 8 + w] = vv;
    }
    __syncthreads();
    if (threadIdx.x < 54) {
        float vv = 0.f;
#pragma unroll
        for (int ww = 0; ww < 8; ww++) vv += red[threadIdx.x * 8 + ww];
        g_part[blockIdx.x * 54 + threadIdx.x] = vv;
    }

    // ---- last-block-done: reduce partials + fold BN into weights ----
    __shared__ bool is_last;
    __threadfence();
    if (threadIdx.x == 0) {
        int prev = atomicAdd(&g_ctr, 1);
        is_last = (prev == gridDim.x - 1);
    }
    __syncthreads();
    if (!is_last) return;

    __shared__ float st[64];
    {
        const int t = threadIdx.x;      // 256 threads
        const int g = t >> 2;           // stat index (0..63, 54 used)
        const int j = t & 3;
        float vv = 0.f;
        if (g < 54)
            for (int b = j; b < STATS_BLOCKS; b += 4)
                vv += g_part[b * 54 + g];
        vv += __shfl_xor_sync(0xffffffffu, vv, 1);
        vv += __shfl_xor_sync(0xffffffffu, vv, 2);
        if (j == 0 && g < 54) st[g] = vv;
    }
    __syncthreads();

    if (threadIdx.x < COUT) {
        const int t = threadIdx.x;
        float wv[9];
#pragma unroll
        for (int k = 0; k < 9; k++) wv[k] = weight[k * COUT + t];
        const float invn = 1.f / (float)n;

        float mean = 0.f;
#pragma unroll
        for (int k = 0; k < 9; k++) mean += st[k] * wv[k];
        mean *= invn;

        float q = 0.f;
        int idx = 9;
#pragma unroll
        for (int jj = 0; jj < 9; jj++)
#pragma unroll
            for (int k = jj; k < 9; k++) {
                float term = st[idx++] * wv[jj] * wv[k];
                q += (jj == k) ? term : 2.f * term;
            }
        float var   = fmaxf(q * invn - mean * mean, 0.f);
        float scale = gamma[t] * rsqrtf(var + BN_EPS);
#pragma unroll
        for (int k = 0; k < 9; k++) g_wf[k * COUT + t] = wv[k] * scale;
        g_bf[t] = beta[t] - mean * scale;
    }
}

// ---------------------------------------------------------------------------
// K4: DENSE output pass, 256-pixel tiles.
//     Phase A: thread t loads its pixel's 9 cells (coalesced LDG.64), stages
//              taps DUPLICATED as (s,s) f32x2 pairs (5 float4, stride 80 B =
//              conflict-free STS.128 per quarter-warp), gets activity + output
//              row from the center cell's .y, ballot-compacts.
//     Phase B: half-warp per ACTIVE pixel; lane computes 4 channels as two
//              packed f32x2 accumulators -> 18 FFMA2 + 5 broadcast LDS.128
//              + 1 coalesced STG.128 per point. Regs capped for 4 blocks/SM.
// ---------------------------------------------------------------------------
__global__ __launch_bounds__(256, 4) void k_output(float4* __restrict__ out) {
    __shared__ float4 sm[TILE * 5];
    __shared__ int   s_meta[TILE];    // (pix << 24) | output row
    __shared__ int   s_cnt;

    const int tid  = threadIdx.x;
    const int lane = tid & 31;
    const int wid  = tid >> 5;
    const int h    = lane >> 4;       // half-warp id (0/1)
    const int cl   = lane & 15;       // float4 channel group

    // BN-folded weights / bias as packed f32x2 pairs
    unsigned long long w01[9], w23[9];
#pragma unroll
    for (int k = 0; k < 9; k++) {
        ulonglong2 wp = reinterpret_cast<const ulonglong2*>(g_wf)[k * 16 + cl];
        w01[k] = wp.x;                // (w[c0], w[c0+1])
        w23[k] = wp.y;                // (w[c0+2], w[c0+3])
    }
    const ulonglong2 bb = reinterpret_cast<const ulonglong2*>(g_bf)[cl];

    const int ntiles = NPIX / TILE;   // 8192
    for (int tile = blockIdx.x; tile < ntiles; tile += gridDim.x) {
        const int q0 = tile * TILE;
        const int y  = q0 >> 11;
        const int x0 = q0 & (WW - 1);

        if (tid == 0) s_cnt = 0;
        __syncthreads();

        // Phase A: coalesced cell loads, duplicated tap staging, compaction
        {
            const float2* rb = g_cell + y * GWC + x0 + tid;
            float s[9];
            int oidx = -1;
#pragma unroll
            for (int r = 0; r < 3; r++)
#pragma unroll
                for (int c = 0; c < 3; c++) {
                    const float2 cell = rb[r * GWC + c];
                    s[r * 3 + c] = cell.x;
                    if (r == 1 && c == 1) oidx = __float_as_int(cell.y);
                }
            sm[tid * 5 + 0] = make_float4(s[0], s[0], s[1], s[1]);
            sm[tid * 5 + 1] = make_float4(s[2], s[2], s[3], s[3]);
            sm[tid * 5 + 2] = make_float4(s[4], s[4], s[5], s[5]);
            sm[tid * 5 + 3] = make_float4(s[6], s[6], s[7], s[7]);
            sm[tid * 5 + 4] = make_float4(s[8], s[8], 0.f, 0.f);

            const bool act = (oidx >= 0);
            const unsigned bal = __ballot_sync(0xffffffffu, act);
            int base;
            if (lane == 0) base = atomicAdd(&s_cnt, __popc(bal));
            base = __shfl_sync(0xffffffffu, base, 0);
            if (act) {
                const int pos = base + __popc(bal & ((1u << lane) - 1u));
                s_meta[pos] = (tid << 24) | oidx;
            }
        }
        __syncthreads();

        // Phase B: half-warp per active pixel, packed f32x2 math
        const int nact = s_cnt;
        for (int sl = wid * 2 + h; sl < nact; sl += 16) {
            const int meta = s_meta[sl];
            const int j    = ((unsigned)meta) >> 24;
            const int oidx = meta & 0xFFFFFF;

            const ulonglong2* tp =
                reinterpret_cast<const ulonglong2*>(&sm[j * 5]);
            const ulonglong2 t0 = tp[0];   // (s0,s0) (s1,s1)
            const ulonglong2 t1 = tp[1];   // (s2,s2) (s3,s3)
            const ulonglong2 t2 = tp[2];   // (s4,s4) (s5,s5)
            const ulonglong2 t3 = tp[3];   // (s6,s6) (s7,s7)
            const ulonglong2 t4 = tp[4];   // (s8,s8) --

            unsigned long long o01 = bb.x, o23 = bb.y;
            FMA2(o01, t0.x, w01[0], o01);  FMA2(o23, t0.x, w23[0], o23);
            FMA2(o01, t0.y, w01[1], o01);  FMA2(o23, t0.y, w23[1], o23);
            FMA2(o01, t1.x, w01[2], o01);  FMA2(o23, t1.x, w23[2], o23);
            FMA2(o01, t1.y, w01[3], o01);  FMA2(o23, t1.y, w23[3], o23);
            FMA2(o01, t2.x, w01[4], o01);  FMA2(o23, t2.x, w23[4], o23);
            FMA2(o01, t2.y, w01[5], o01);  FMA2(o23, t2.y, w23[5], o23);
            FMA2(o01, t3.x, w01[6], o01);  FMA2(o23, t3.x, w23[6], o23);
            FMA2(o01, t3.y, w01[7], o01);  FMA2(o23, t3.y, w23[7], o23);
            FMA2(o01, t4.x, w01[8], o01);  FMA2(o23, t4.x, w23[8], o23);

            const float2 a = *reinterpret_cast<float2*>(&o01);
            const float2 b = *reinterpret_cast<float2*>(&o23);
            float4 o = make_float4(fmaxf(a.x, 0.f), fmaxf(a.y, 0.f),
                                   fmaxf(b.x, 0.f), fmaxf(b.y, 0.f));
            __stcs(&out[(size_t)oidx * 16 + cl], o);
        }
        __syncthreads();
    }
}

// ---------------------------------------------------------------------------
// Launch: inputs are feats[N,1] f32, weight[9,1,64] f32, gamma[64], beta[64],
//         coords[N,2] i32. Output: [N,64] f32.
// ---------------------------------------------------------------------------
extern "C" void kernel_launch(void* const* d_in, const int* in_sizes, int n_in,
                              void* d_out, int out_size) {
    const float* feats  = (const float*)d_in[0];
    const float* weight = (const float*)d_in[1];
    const float* gamma  = (const float*)d_in[2];
    const float* beta   = (const float*)d_in[3];
    const int2*  coords = (const int2*)d_in[4];
    const int n = in_sizes[0];   // N (C_IN = 1)

    k_zero<<<1480, 256>>>();
    k_scatter<<<(n + 255) / 256, 256>>>(coords, feats, n);
    k_stats<<<STATS_BLOCKS, 256>>>(weight, gamma, beta, n);
    k_output<<<1480, 256>>>((float4*)d_out);
}

// round 8
// speedup vs baseline: 1.1025x; 1.1025x over previous
#include <cuda_runtime.h>

// Problem constants (fixed by the dataset)
#define HH   1024
#define WW   2048
#define GW2  2052            // padded row stride (multiple of 4 for aligned float4)
#define GH   (HH + 2)        // padded grid height = 1026
#define GSZ  (GH * GW2)      // 2,105,352 floats
#define NPIX (HH * WW)       // 2,097,152
#define COUT 64
#define BN_EPS 1e-5f
#define STATS_BLOCKS 592
#define NWARP 8              // warps per block in k_output

// Scratch (static __device__ arrays — no allocation)
__device__ float g_grid[GSZ];                // ~8.4 MB padded dense grid (L2-resident)
__device__ int   g_idx[NPIX];                // 8 MB pixel -> output-row index (-1 = empty)
__device__ float g_part[STATS_BLOCKS * 54];  // per-block stat partials
__device__ float g_wf[9 * COUT];             // BN-folded weights
__device__ float g_bf[COUT];                 // BN-folded bias
__device__ int   g_ctr;                      // last-block-done counter

// ---------------------------------------------------------------------------
// K0: zero the padded grid, fill idx with -1, reset the stats counter
// ---------------------------------------------------------------------------
__global__ void k_zero() {
    if (blockIdx.x == 0 && threadIdx.x == 0) g_ctr = 0;
    const int n4g = GSZ / 4;
    const int n4i = NPIX / 4;
    float4 z  = make_float4(0.f, 0.f, 0.f, 0.f);
    int4   mi = make_int4(-1, -1, -1, -1);
    const int tid = blockIdx.x * blockDim.x + threadIdx.x;
    const int str = gridDim.x * blockDim.x;
    for (int j = tid; j < n4g; j += str)
        reinterpret_cast<float4*>(g_grid)[j] = z;
    for (int j = tid; j < n4i; j += str)
        reinterpret_cast<int4*>(g_idx)[j] = mi;
}

// ---------------------------------------------------------------------------
// K1: scatter active features into the padded grid + record output row index
// ---------------------------------------------------------------------------
__global__ void k_scatter(const int2* __restrict__ coords,
                          const float* __restrict__ feats, int n) {
    int i = blockIdx.x * blockDim.x + threadIdx.x;
    if (i < n) {
        int2 c = coords[i];                        // c.x = y, c.y = x
        g_grid[(c.x + 1) * GW2 + (c.y + 1)] = feats[i];
        g_idx[c.x * WW + c.y] = i;
    }
}

// ---------------------------------------------------------------------------
// K2: DENSE vectorized stats scan — each thread handles 4 consecutive pixels
//     with 6 aligned LDG.128 (3 rows x 2 float4) + 1 int4 (idx as mask).
//     Accumulates sum9[9] + upper-tri second moment M[45] in fixed order
//     (deterministic). LAST block reduces partials + folds BN into weights.
// ---------------------------------------------------------------------------
__global__ __launch_bounds__(256) void k_stats(
        const float* __restrict__ weight,   // [9,1,64]
        const float* __restrict__ gamma,
        const float* __restrict__ beta, int n) {
    float acc[54];
#pragma unroll
    for (int i = 0; i < 54; i++) acc[i] = 0.f;

    const int tid    = blockIdx.x * blockDim.x + threadIdx.x;
    const int stride = gridDim.x * blockDim.x;
    const int nquad  = NPIX / 4;

    for (int Q = tid; Q < nquad; Q += stride) {
        const int q = Q * 4;
        const int y = q >> 11;           // WW = 2048
        const int x = q & (WW - 1);      // multiple of 4
        const float* rb = g_grid + y * GW2 + x;   // row base, 16B-aligned

        float4 a0 = *reinterpret_cast<const float4*>(rb);
        float4 a1 = *reinterpret_cast<const float4*>(rb + 4);
        float4 b0 = *reinterpret_cast<const float4*>(rb + GW2);
        float4 b1 = *reinterpret_cast<const float4*>(rb + GW2 + 4);
        float4 c0 = *reinterpret_cast<const float4*>(rb + 2 * GW2);
        float4 c1 = *reinterpret_cast<const float4*>(rb + 2 * GW2 + 4);
        int4 iv = *reinterpret_cast<const int4*>(g_idx + q);

        float r0[8] = {a0.x, a0.y, a0.z, a0.w, a1.x, a1.y, a1.z, a1.w};
        float r1[8] = {b0.x, b0.y, b0.z, b0.w, b1.x, b1.y, b1.z, b1.w};
        float r2[8] = {c0.x, c0.y, c0.z, c0.w, c1.x, c1.y, c1.z, c1.w};
        float m[4]  = {iv.x >= 0 ? 1.f : 0.f, iv.y >= 0 ? 1.f : 0.f,
                       iv.z >= 0 ? 1.f : 0.f, iv.w >= 0 ? 1.f : 0.f};

#pragma unroll
        for (int i = 0; i < 4; i++) {
            float s[9];
#pragma unroll
            for (int t = 0; t < 3; t++) {
                s[0 + t] = r0[i + t] * m[i];
                s[3 + t] = r1[i + t] * m[i];
                s[6 + t] = r2[i + t] * m[i];
            }
#pragma unroll
            for (int k = 0; k < 9; k++) acc[k] += s[k];
            int idx = 9;
#pragma unroll
            for (int j = 0; j < 9; j++)
#pragma unroll
                for (int k = j; k < 9; k++) acc[idx++] += s[j] * s[k];
        }
    }

    // block reduction: warp shfl -> shared -> per-block partial
    __shared__ float red[54 * 8];
    const int w = threadIdx.x >> 5, lane = threadIdx.x & 31;
#pragma unroll
    for (int i = 0; i < 54; i++) {
        float v = acc[i];
#pragma unroll
        for (int o = 16; o; o >>= 1) v += __shfl_xor_sync(0xffffffffu, v, o);
        if (lane == 0) red[i * 8 + w] = v;
    }
    __syncthreads();
    if (threadIdx.x < 54) {
        float v = 0.f;
#pragma unroll
        for (int ww = 0; ww < 8; ww++) v += red[threadIdx.x * 8 + ww];
        g_part[blockIdx.x * 54 + threadIdx.x] = v;
    }

    // ---- last-block-done: reduce partials + fold BN into weights ----
    __shared__ bool is_last;
    __threadfence();
    if (threadIdx.x == 0) {
        int prev = atomicAdd(&g_ctr, 1);
        is_last = (prev == gridDim.x - 1);
    }
    __syncthreads();
    if (!is_last) return;

    __shared__ float st[64];
    {
        const int t = threadIdx.x;      // 256 threads
        const int g = t >> 2;           // stat index (0..63, 54 used)
        const int j = t & 3;
        float v = 0.f;
        if (g < 54)
            for (int b = j; b < STATS_BLOCKS; b += 4)
                v += g_part[b * 54 + g];
        v += __shfl_xor_sync(0xffffffffu, v, 1);
        v += __shfl_xor_sync(0xffffffffu, v, 2);
        if (j == 0 && g < 54) st[g] = v;
    }
    __syncthreads();

    if (threadIdx.x < COUT) {
        const int t = threadIdx.x;
        float wv[9];
#pragma unroll
        for (int k = 0; k < 9; k++) wv[k] = weight[k * COUT + t];
        const float invn = 1.f / (float)n;

        float mean = 0.f;
#pragma unroll
        for (int k = 0; k < 9; k++) mean += st[k] * wv[k];
        mean *= invn;

        float q = 0.f;
        int idx = 9;
#pragma unroll
        for (int jj = 0; jj < 9; jj++)
#pragma unroll
            for (int k = jj; k < 9; k++) {
                float term = st[idx++] * wv[jj] * wv[k];
                q += (jj == k) ? term : 2.f * term;
            }
        float var   = fmaxf(q * invn - mean * mean, 0.f);
        float scale = gamma[t] * rsqrtf(var + BN_EPS);
#pragma unroll
        for (int k = 0; k < 9; k++) g_wf[k * COUT + t] = wv[k] * scale;
        g_bf[t] = beta[t] - mean * scale;
    }
}

// ---------------------------------------------------------------------------
// K4: DENSE output pass, WARP-AUTONOMOUS 32-pixel tiles (no block barriers,
//     no block atomics — each warp owns a private smem slot).
//     Phase A: lane loads its pixel's idx; ONLY active lanes gather the 9
//              taps (3 rows, coalesced within cache lines) and stage them as
//              3 float4 (stride 48 B: conflict-free STS.128); ballot-compacts
//              (pix<<24 | row) into warp-private meta.
//     Phase B: half-warp per ACTIVE pixel; lane computes 4 channels;
//              3 broadcast LDS.128 + 36 FMA + 1 coalesced STG.128 (256 B row,
//              streaming) per point.
// ---------------------------------------------------------------------------
__global__ __launch_bounds__(256) void k_output(float4* __restrict__ out) {
    __shared__ float4 sm[NWARP][32 * 3];
    __shared__ int   s_meta[NWARP][32];

    const int tid  = threadIdx.x;
    const int lane = tid & 31;
    const int wid  = tid >> 5;
    const int h    = lane >> 4;       // half-warp id (0/1)
    const int cl   = lane & 15;       // float4 channel group

    float4 w4[9];
#pragma unroll
    for (int k = 0; k < 9; k++)
        w4[k] = reinterpret_cast<const float4*>(g_wf)[k * 16 + cl];
    const float4 b4 = reinterpret_cast<const float4*>(g_bf)[cl];

    const int ntiles = NPIX / 32;     // 65536 warp-tiles (64 per grid row)
    const int wstride = (gridDim.x * blockDim.x) >> 5;

    for (int tile = (blockIdx.x * blockDim.x + tid) >> 5; tile < ntiles;
         tile += wstride) {
        const int q0 = tile * 32;
        const int y  = q0 >> 11;
        const int x0 = q0 & (WW - 1);

        // Phase A: activity-gated tap staging + warp-local compaction
        const int  oidx = g_idx[q0 + lane];
        const bool act  = (oidx >= 0);
        const unsigned bal = __ballot_sync(0xffffffffu, act);
        if (act) {
            const float* rb = g_grid + y * GW2 + x0 + lane;
            float s[9];
#pragma unroll
            for (int r = 0; r < 3; r++)
#pragma unroll
                for (int c = 0; c < 3; c++)
                    s[r * 3 + c] = rb[r * GW2 + c];
            sm[wid][lane * 3 + 0] = make_float4(s[0], s[1], s[2], s[3]);
            sm[wid][lane * 3 + 1] = make_float4(s[4], s[5], s[6], s[7]);
            sm[wid][lane * 3 + 2] = make_float4(s[8], 0.f, 0.f, 0.f);

            const int pos = __popc(bal & ((1u << lane) - 1u));
            s_meta[wid][pos] = (lane << 24) | oidx;
        }
        __syncwarp();

        // Phase B: half-warp per active pixel
        const int nact = __popc(bal);
        for (int sl = h; sl < nact; sl += 2) {
            const int meta = s_meta[wid][sl];
            const int j    = ((unsigned)meta) >> 24;
            const int row  = meta & 0xFFFFFF;
            const float4 A = sm[wid][j * 3 + 0];
            const float4 B = sm[wid][j * 3 + 1];
            const float s8 = sm[wid][j * 3 + 2].x;

            float4 o = b4;
            o.x = fmaf(A.x, w4[0].x, o.x); o.y = fmaf(A.x, w4[0].y, o.y);
            o.z = fmaf(A.x, w4[0].z, o.z); o.w = fmaf(A.x, w4[0].w, o.w);
            o.x = fmaf(A.y, w4[1].x, o.x); o.y = fmaf(A.y, w4[1].y, o.y);
            o.z = fmaf(A.y, w4[1].z, o.z); o.w = fmaf(A.y, w4[1].w, o.w);
            o.x = fmaf(A.z, w4[2].x, o.x); o.y = fmaf(A.z, w4[2].y, o.y);
            o.z = fmaf(A.z, w4[2].z, o.z); o.w = fmaf(A.z, w4[2].w, o.w);
            o.x = fmaf(A.w, w4[3].x, o.x); o.y = fmaf(A.w, w4[3].y, o.y);
            o.z = fmaf(A.w, w4[3].z, o.z); o.w = fmaf(A.w, w4[3].w, o.w);
            o.x = fmaf(B.x, w4[4].x, o.x); o.y = fmaf(B.x, w4[4].y, o.y);
            o.z = fmaf(B.x, w4[4].z, o.z); o.w = fmaf(B.x, w4[4].w, o.w);
            o.x = fmaf(B.y, w4[5].x, o.x); o.y = fmaf(B.y, w4[5].y, o.y);
            o.z = fmaf(B.y, w4[5].z, o.z); o.w = fmaf(B.y, w4[5].w, o.w);
            o.x = fmaf(B.z, w4[6].x, o.x); o.y = fmaf(B.z, w4[6].y, o.y);
            o.z = fmaf(B.z, w4[6].z, o.z); o.w = fmaf(B.z, w4[6].w, o.w);
            o.x = fmaf(B.w, w4[7].x, o.x); o.y = fmaf(B.w, w4[7].y, o.y);
            o.z = fmaf(B.w, w4[7].z, o.z); o.w = fmaf(B.w, w4[7].w, o.w);
            o.x = fmaf(s8,  w4[8].x, o.x); o.y = fmaf(s8,  w4[8].y, o.y);
            o.z = fmaf(s8,  w4[8].z, o.z); o.w = fmaf(s8,  w4[8].w, o.w);

            o.x = fmaxf(o.x, 0.f); o.y = fmaxf(o.y, 0.f);
            o.z = fmaxf(o.z, 0.f); o.w = fmaxf(o.w, 0.f);
            __stcs(&out[(size_t)row * 16 + cl], o);
        }
        __syncwarp();
    }
}

// ---------------------------------------------------------------------------
// Launch: inputs are feats[N,1] f32, weight[9,1,64] f32, gamma[64], beta[64],
//         coords[N,2] i32. Output: [N,64] f32.
// ---------------------------------------------------------------------------
extern "C" void kernel_launch(void* const* d_in, const int* in_sizes, int n_in,
                              void* d_out, int out_size) {
    const float* feats  = (const float*)d_in[0];
    const float* weight = (const float*)d_in[1];
    const float* gamma  = (const float*)d_in[2];
    const float* beta   = (const float*)d_in[3];
    const int2*  coords = (const int2*)d_in[4];
    const int n = in_sizes[0];   // N (C_IN = 1)

    k_zero<<<1480, 256>>>();
    k_scatter<<<(n + 255) / 256, 256>>>(coords, feats, n);
    k_stats<<<STATS_BLOCKS, 256>>>(weight, gamma, beta, n);
    k_output<<<1480, 256>>>((float4*)d_out);
}

// round 9
// speedup vs baseline: 1.1081x; 1.0051x over previous
#include <cuda_runtime.h>

// Problem constants (fixed by the dataset)
#define HH   1024
#define WW   2048
#define GW2  2052            // padded row stride (multiple of 4 for aligned float4)
#define GH   (HH + 2)        // padded grid height = 1026
#define GSZ  (GH * GW2)      // 2,105,352 floats
#define NPIX (HH * WW)       // 2,097,152
#define COUT 64
#define BN_EPS 1e-5f
#define STATS_BLOCKS 592
#define TILE 256

// Scratch (static __device__ arrays — no allocation)
__device__ float g_grid[GSZ];                // ~8.4 MB padded dense grid (L2-resident)
__device__ int   g_idx[NPIX];                // 8 MB pixel -> output-row index (-1 = empty)
__device__ float g_part[STATS_BLOCKS * 54];  // per-block stat partials
__device__ float g_wf[9 * COUT];             // BN-folded weights
__device__ float g_bf[COUT];                 // BN-folded bias
__device__ int   g_ctr;                      // last-block-done counter

// ---------------------------------------------------------------------------
// K0: zero the padded grid, fill idx with -1, reset the stats counter
// ---------------------------------------------------------------------------
__global__ void k_zero() {
    if (blockIdx.x == 0 && threadIdx.x == 0) g_ctr = 0;
    const int n4g = GSZ / 4;
    const int n4i = NPIX / 4;
    float4 z  = make_float4(0.f, 0.f, 0.f, 0.f);
    int4   mi = make_int4(-1, -1, -1, -1);
    const int tid = blockIdx.x * blockDim.x + threadIdx.x;
    const int str = gridDim.x * blockDim.x;
    for (int j = tid; j < n4g; j += str)
        reinterpret_cast<float4*>(g_grid)[j] = z;
    for (int j = tid; j < n4i; j += str)
        reinterpret_cast<int4*>(g_idx)[j] = mi;
}

// ---------------------------------------------------------------------------
// K1: scatter active features into the padded grid + record output row index
// ---------------------------------------------------------------------------
__global__ void k_scatter(const int2* __restrict__ coords,
                          const float* __restrict__ feats, int n) {
    int i = blockIdx.x * blockDim.x + threadIdx.x;
    if (i < n) {
        int2 c = coords[i];                        // c.x = y, c.y = x
        g_grid[(c.x + 1) * GW2 + (c.y + 1)] = feats[i];
        g_idx[c.x * WW + c.y] = i;
    }
}

// ---------------------------------------------------------------------------
// K2: DENSE vectorized stats scan — each thread handles 4 consecutive pixels
//     with 6 aligned LDG.128 (3 rows x 2 float4) + 1 int4 (idx as mask).
//     Accumulates sum9[9] + upper-tri second moment M[45] in fixed order
//     (deterministic). LAST block reduces partials + folds BN into weights.
// ---------------------------------------------------------------------------
__global__ __launch_bounds__(256) void k_stats(
        const float* __restrict__ weight,   // [9,1,64]
        const float* __restrict__ gamma,
        const float* __restrict__ beta, int n) {
    float acc[54];
#pragma unroll
    for (int i = 0; i < 54; i++) acc[i] = 0.f;

    const int tid    = blockIdx.x * blockDim.x + threadIdx.x;
    const int stride = gridDim.x * blockDim.x;
    const int nquad  = NPIX / 4;

    for (int Q = tid; Q < nquad; Q += stride) {
        const int q = Q * 4;
        const int y = q >> 11;           // WW = 2048
        const int x = q & (WW - 1);      // multiple of 4
        const float* rb = g_grid + y * GW2 + x;   // row base, 16B-aligned

        float4 a0 = *reinterpret_cast<const float4*>(rb);
        float4 a1 = *reinterpret_cast<const float4*>(rb + 4);
        float4 b0 = *reinterpret_cast<const float4*>(rb + GW2);
        float4 b1 = *reinterpret_cast<const float4*>(rb + GW2 + 4);
        float4 c0 = *reinterpret_cast<const float4*>(rb + 2 * GW2);
        float4 c1 = *reinterpret_cast<const float4*>(rb + 2 * GW2 + 4);
        int4 iv = *reinterpret_cast<const int4*>(g_idx + q);

        float r0[8] = {a0.x, a0.y, a0.z, a0.w, a1.x, a1.y, a1.z, a1.w};
        float r1[8] = {b0.x, b0.y, b0.z, b0.w, b1.x, b1.y, b1.z, b1.w};
        float r2[8] = {c0.x, c0.y, c0.z, c0.w, c1.x, c1.y, c1.z, c1.w};
        float m[4]  = {iv.x >= 0 ? 1.f : 0.f, iv.y >= 0 ? 1.f : 0.f,
                       iv.z >= 0 ? 1.f : 0.f, iv.w >= 0 ? 1.f : 0.f};

#pragma unroll
        for (int i = 0; i < 4; i++) {
            float s[9];
#pragma unroll
            for (int t = 0; t < 3; t++) {
                s[0 + t] = r0[i + t] * m[i];
                s[3 + t] = r1[i + t] * m[i];
                s[6 + t] = r2[i + t] * m[i];
            }
#pragma unroll
            for (int k = 0; k < 9; k++) acc[k] += s[k];
            int idx = 9;
#pragma unroll
            for (int j = 0; j < 9; j++)
#pragma unroll
                for (int k = j; k < 9; k++) acc[idx++] += s[j] * s[k];
        }
    }

    // block reduction: warp shfl -> shared -> per-block partial
    __shared__ float red[54 * 8];
    const int w = threadIdx.x >> 5, lane = threadIdx.x & 31;
#pragma unroll
    for (int i = 0; i < 54; i++) {
        float v = acc[i];
#pragma unroll
        for (int o = 16; o; o >>= 1) v += __shfl_xor_sync(0xffffffffu, v, o);
        if (lane == 0) red[i * 8 + w] = v;
    }
    __syncthreads();
    if (threadIdx.x < 54) {
        float v = 0.f;
#pragma unroll
        for (int ww = 0; ww < 8; ww++) v += red[threadIdx.x * 8 + ww];
        g_part[blockIdx.x * 54 + threadIdx.x] = v;
    }

    // ---- last-block-done: reduce partials + fold BN into weights ----
    __shared__ bool is_last;
    __threadfence();
    if (threadIdx.x == 0) {
        int prev = atomicAdd(&g_ctr, 1);
        is_last = (prev == gridDim.x - 1);
    }
    __syncthreads();
    if (!is_last) return;

    __shared__ float st[64];
    {
        const int t = threadIdx.x;      // 256 threads
        const int g = t >> 2;           // stat index (0..63, 54 used)
        const int j = t & 3;
        float v = 0.f;
        if (g < 54)
            for (int b = j; b < STATS_BLOCKS; b += 4)
                v += g_part[b * 54 + g];
        v += __shfl_xor_sync(0xffffffffu, v, 1);
        v += __shfl_xor_sync(0xffffffffu, v, 2);
        if (j == 0 && g < 54) st[g] = v;
    }
    __syncthreads();

    if (threadIdx.x < COUT) {
        const int t = threadIdx.x;
        float wv[9];
#pragma unroll
        for (int k = 0; k < 9; k++) wv[k] = weight[k * COUT + t];
        const float invn = 1.f / (float)n;

        float mean = 0.f;
#pragma unroll
        for (int k = 0; k < 9; k++) mean += st[k] * wv[k];
        mean *= invn;

        float q = 0.f;
        int idx = 9;
#pragma unroll
        for (int jj = 0; jj < 9; jj++)
#pragma unroll
            for (int k = jj; k < 9; k++) {
                float term = st[idx++] * wv[jj] * wv[k];
                q += (jj == k) ? term : 2.f * term;
            }
        float var   = fmaxf(q * invn - mean * mean, 0.f);
        float scale = gamma[t] * rsqrtf(var + BN_EPS);
#pragma unroll
        for (int k = 0; k < 9; k++) g_wf[k * COUT + t] = wv[k] * scale;
        g_bf[t] = beta[t] - mean * scale;
    }
}

// ---------------------------------------------------------------------------
// K4: DENSE output pass, 256-pixel tiles (R5 structure, Phase A gated).
//     Phase A: thread t reads its pixel's idx; ONLY active threads gather
//              the 9 taps (coalesced row loads) and stage them as 3 float4
//              (stride 48 B: conflict-free STS.128); ballot-compacts
//              (pix<<24 | row).
//     Phase B: half-warp per ACTIVE pixel; lane computes 4 channels;
//              3 broadcast LDS.128 + 36 FMA + 1 coalesced STG.128 (256 B
//              row, streaming) per point; unrolled x2.
// ---------------------------------------------------------------------------
__global__ __launch_bounds__(256) void k_output(float4* __restrict__ out) {
    __shared__ float4 sm[TILE * 3];
    __shared__ int   s_meta[TILE];    // (pix << 24) | output row
    __shared__ int   s_cnt;

    const int tid  = threadIdx.x;
    const int lane = tid & 31;
    const int wid  = tid >> 5;
    const int h    = lane >> 4;       // half-warp id (0/1)
    const int cl   = lane & 15;       // float4 channel group

    float4 w4[9];
#pragma unroll
    for (int k = 0; k < 9; k++)
        w4[k] = reinterpret_cast<const float4*>(g_wf)[k * 16 + cl];
    const float4 b4 = reinterpret_cast<const float4*>(g_bf)[cl];

    const int ntiles = NPIX / TILE;   // 8192
    for (int tile = blockIdx.x; tile < ntiles; tile += gridDim.x) {
        const int q0 = tile * TILE;
        const int y  = q0 >> 11;
        const int x0 = q0 & (WW - 1);

        if (tid == 0) s_cnt = 0;
        __syncthreads();

        // Phase A: activity-gated tap staging + compaction
        {
            const int  oidx = g_idx[q0 + tid];
            const bool act  = (oidx >= 0);
            if (act) {
                const float* rb = g_grid + y * GW2 + x0 + tid;
                float s[9];
#pragma unroll
                for (int r = 0; r < 3; r++)
#pragma unroll
                    for (int c = 0; c < 3; c++)
                        s[r * 3 + c] = rb[r * GW2 + c];
                sm[tid * 3 + 0] = make_float4(s[0], s[1], s[2], s[3]);
                sm[tid * 3 + 1] = make_float4(s[4], s[5], s[6], s[7]);
                sm[tid * 3 + 2] = make_float4(s[8], 0.f, 0.f, 0.f);
            }
            const unsigned bal = __ballot_sync(0xffffffffu, act);
            int base;
            if (lane == 0) base = atomicAdd(&s_cnt, __popc(bal));
            base = __shfl_sync(0xffffffffu, base, 0);
            if (act) {
                const int pos = base + __popc(bal & ((1u << lane) - 1u));
                s_meta[pos] = (tid << 24) | oidx;
            }
        }
        __syncthreads();

        // Phase B: half-warp per active pixel
        const int nact = s_cnt;
#pragma unroll 2
        for (int sl = wid * 2 + h; sl < nact; sl += 16) {
            const int meta = s_meta[sl];
            const int j    = ((unsigned)meta) >> 24;
            const int oidx = meta & 0xFFFFFF;
            const float4 A = sm[j * 3 + 0];
            const float4 B = sm[j * 3 + 1];
            const float s8 = sm[j * 3 + 2].x;

            float4 o = b4;
            o.x = fmaf(A.x, w4[0].x, o.x); o.y = fmaf(A.x, w4[0].y, o.y);
            o.z = fmaf(A.x, w4[0].z, o.z); o.w = fmaf(A.x, w4[0].w, o.w);
            o.x = fmaf(A.y, w4[1].x, o.x); o.y = fmaf(A.y, w4[1].y, o.y);
            o.z = fmaf(A.y, w4[1].z, o.z); o.w = fmaf(A.y, w4[1].w, o.w);
            o.x = fmaf(A.z, w4[2].x, o.x); o.y = fmaf(A.z, w4[2].y, o.y);
            o.z = fmaf(A.z, w4[2].z, o.z); o.w = fmaf(A.z, w4[2].w, o.w);
            o.x = fmaf(A.w, w4[3].x, o.x); o.y = fmaf(A.w, w4[3].y, o.y);
            o.z = fmaf(A.w, w4[3].z, o.z); o.w = fmaf(A.w, w4[3].w, o.w);
            o.x = fmaf(B.x, w4[4].x, o.x); o.y = fmaf(B.x, w4[4].y, o.y);
            o.z = fmaf(B.x, w4[4].z, o.z); o.w = fmaf(B.x, w4[4].w, o.w);
            o.x = fmaf(B.y, w4[5].x, o.x); o.y = fmaf(B.y, w4[5].y, o.y);
            o.z = fmaf(B.y, w4[5].z, o.z); o.w = fmaf(B.y, w4[5].w, o.w);
            o.x = fmaf(B.z, w4[6].x, o.x); o.y = fmaf(B.z, w4[6].y, o.y);
            o.z = fmaf(B.z, w4[6].z, o.z); o.w = fmaf(B.z, w4[6].w, o.w);
            o.x = fmaf(B.w, w4[7].x, o.x); o.y = fmaf(B.w, w4[7].y, o.y);
            o.z = fmaf(B.w, w4[7].z, o.z); o.w = fmaf(B.w, w4[7].w, o.w);
            o.x = fmaf(s8,  w4[8].x, o.x); o.y = fmaf(s8,  w4[8].y, o.y);
            o.z = fmaf(s8,  w4[8].z, o.z); o.w = fmaf(s8,  w4[8].w, o.w);

            o.x = fmaxf(o.x, 0.f); o.y = fmaxf(o.y, 0.f);
            o.z = fmaxf(o.z, 0.f); o.w = fmaxf(o.w, 0.f);
            __stcs(&out[(size_t)oidx * 16 + cl], o);
        }
        __syncthreads();
    }
}

// ---------------------------------------------------------------------------
// Launch: inputs are feats[N,1] f32, weight[9,1,64] f32, gamma[64], beta[64],
//         coords[N,2] i32. Output: [N,64] f32.
// ---------------------------------------------------------------------------
extern "C" void kernel_launch(void* const* d_in, const int* in_sizes, int n_in,
                              void* d_out, int out_size) {
    const float* feats  = (const float*)d_in[0];
    const float* weight = (const float*)d_in[1];
    const float* gamma  = (const float*)d_in[2];
    const float* beta   = (const float*)d_in[3];
    const int2*  coords = (const int2*)d_in[4];
    const int n = in_sizes[0];   // N (C_IN = 1)

    k_zero<<<1480, 256>>>();
    k_scatter<<<(n + 255) / 256, 256>>>(coords, feats, n);
    k_stats<<<STATS_BLOCKS, 256>>>(weight, gamma, beta, n);
    k_output<<<1184, 256>>>((float4*)d_out);
}